// round 1
// baseline (speedup 1.0000x reference)
#include <cuda_runtime.h>
#include <cuda_bf16.h>

#define MAXN 1000000

// Scratch (no device allocations allowed in kernel_launch)
__device__ int   g_ideg[MAXN];   // integer degree incl. self-loop
__device__ float g_dinv[MAXN];   // rsqrt(deg)
__device__ float g_y[MAXN];      // x * W * dinv  (pre-scaled messages)
__device__ float g_S[MAXN];      // sum of incoming y[src]

// ---------------------------------------------------------------------------
// Pass 1: init  deg=1 (self-loop), S=0
__global__ void k_init(int n) {
    int i = blockIdx.x * blockDim.x + threadIdx.x;
    if (i < n) {
        g_ideg[i] = 1;
        g_S[i] = 0.0f;
    }
}

// ---------------------------------------------------------------------------
// Pass 2: degree count over destination nodes. dst is read coalesced as int4.
__global__ void k_degree(const int* __restrict__ dst, int e4, int e) {
    int i = blockIdx.x * blockDim.x + threadIdx.x;
    if (i < e4) {
        int4 d = reinterpret_cast<const int4*>(dst)[i];
        atomicAdd(&g_ideg[d.x], 1);
        atomicAdd(&g_ideg[d.y], 1);
        atomicAdd(&g_ideg[d.z], 1);
        atomicAdd(&g_ideg[d.w], 1);
    }
    // tail (E not divisible by 4)
    int t = e4 * 4 + i;
    if (i < (e - e4 * 4)) {
        atomicAdd(&g_ideg[dst[t]], 1);
    }
}

// ---------------------------------------------------------------------------
// Pass 3: per-node precompute  dinv = rsqrt(deg),  y = x*W*dinv
__global__ void k_node(const float* __restrict__ x,
                       const float* __restrict__ W, int n) {
    int i = blockIdx.x * blockDim.x + threadIdx.x;
    if (i < n) {
        float w = __ldg(W);
        float dinv = rsqrtf((float)g_ideg[i]);
        g_dinv[i] = dinv;
        g_y[i] = x[i] * w * dinv;
    }
}

// ---------------------------------------------------------------------------
// Pass 4: edge scatter  S[dst] += y[src].
// src/dst read coalesced (int4); y gather + S atomics hit the 4MB L2-resident
// arrays.
__global__ void k_scatter(const int* __restrict__ src,
                          const int* __restrict__ dst, int e4, int e) {
    int i = blockIdx.x * blockDim.x + threadIdx.x;
    if (i < e4) {
        int4 s = reinterpret_cast<const int4*>(src)[i];
        int4 d = reinterpret_cast<const int4*>(dst)[i];
        float ya = __ldg(&g_y[s.x]);
        float yb = __ldg(&g_y[s.y]);
        float yc = __ldg(&g_y[s.z]);
        float yd = __ldg(&g_y[s.w]);
        atomicAdd(&g_S[d.x], ya);
        atomicAdd(&g_S[d.y], yb);
        atomicAdd(&g_S[d.z], yc);
        atomicAdd(&g_S[d.w], yd);
    }
    int t = e4 * 4 + i;
    if (i < (e - e4 * 4)) {
        atomicAdd(&g_S[dst[t]], __ldg(&g_y[src[t]]));
    }
}

// ---------------------------------------------------------------------------
// Pass 5: out = sigmoid(dinv*(S + y) + b)   (self-loop contributes y[i])
__global__ void k_final(float* __restrict__ out,
                        const float* __restrict__ b, int n) {
    int i = blockIdx.x * blockDim.x + threadIdx.x;
    if (i < n) {
        float z = g_dinv[i] * (g_S[i] + g_y[i]) + __ldg(b);
        out[i] = 1.0f / (1.0f + __expf(-z));
    }
}

// ---------------------------------------------------------------------------
extern "C" void kernel_launch(void* const* d_in, const int* in_sizes, int n_in,
                              void* d_out, int out_size) {
    const float* x    = (const float*)d_in[0];
    const int*   eidx = (const int*)  d_in[1];
    const float* W    = (const float*)d_in[2];
    const float* b    = (const float*)d_in[3];
    float* out = (float*)d_out;

    int n = in_sizes[0];          // N nodes
    int e = in_sizes[1] / 2;      // E edges (edge_index is [2, E])
    const int* src = eidx;
    const int* dst = eidx + e;

    int e4 = e / 4;

    const int TPB = 256;
    int gn = (n + TPB - 1) / TPB;
    int ge = (e4 + TPB - 1) / TPB;

    k_init   <<<gn, TPB>>>(n);
    k_degree <<<ge, TPB>>>(dst, e4, e);
    k_node   <<<gn, TPB>>>(x, W, n);
    k_scatter<<<ge, TPB>>>(src, dst, e4, e);
    k_final  <<<gn, TPB>>>(out, b, n);
}